// round 5
// baseline (speedup 1.0000x reference)
#include <cuda_runtime.h>

#define N_USERS   50000
#define DEG       32
#define N_EDGES   (N_USERS * DEG)
#define N_SERVERS 512

#define NBLK    296                                  // 2 CTAs per SM, single wave
#define NTHR    1024
#define NWARPS  (NTHR / 32)
#define NWARP_G (NBLK * NWARPS)                      // 9472 warps
#define ITERS   ((N_USERS + NWARP_G - 1) / NWARP_G)  // 6

// Persistent state (allocation-free; self-cleaning, no zeroing kernel)
__device__ float        g_ssum[N_SERVERS];  // zero-init; re-zeroed each run
__device__ double       g_acc;              // zero-init; re-zeroed each run
__device__ unsigned     g_cnt;              // barrier counter, self-resetting
__device__ volatile int g_flag;             // barrier sense, returns to 0 each run

// ---------------------------------------------------------------------------
// dtype detection for edge_index: user_index = repeat(arange(50000), 32).
// As u64 words, word[16] (bytes 128..135):
//   int64 storage: user64[16] = 0
//   int32 storage: packs user32[32]=1,user32[33]=1 -> 0x0000000100000001
// ---------------------------------------------------------------------------
__device__ __forceinline__ bool idx_is64(const void* eidx) {
    return ((const unsigned long long*)eidx)[16] == 0ull;
}
__device__ __forceinline__ int load_server(const void* eidx, int e, bool is64) {
    if (is64) return (int)((const long long*)eidx)[N_EDGES + e];
    return ((const int*)eidx)[N_EDGES + e];
}

// Sense-reversing grid barrier; every thread fences so all REDG/atomic traffic
// issued before the barrier is globally visible after it.
// Valid: 296 CTAs = exactly one wave (2 CTAs/SM by launch_bounds + smem).
__device__ __forceinline__ void grid_barrier(int sense) {
    __threadfence();
    __syncthreads();
    if (threadIdx.x == 0) {
        unsigned t = atomicAdd(&g_cnt, 1u);
        if (t == NBLK - 1) {
            atomicExch(&g_cnt, 0u);
            __threadfence();
            g_flag = sense;
        } else {
            while (g_flag != sense) { }
        }
        __threadfence();
    }
    __syncthreads();
}

// Accurate log2(1+x) for small x (relative truncation err < x^4/5):
// avoids both MUFU LG2's absolute-error blowup (R3 bug) and the ~40-instr
// precise log2f sequence (R4 cost).
__device__ __forceinline__ float log2_1p(float x) {
    if (x < 0.02f) {
        const float c1 =  1.4426950408889634f;   //  1/ln2
        const float c2 = -0.7213475204444817f;   // -1/(2 ln2)
        const float c3 =  0.4808983469629878f;   //  1/(3 ln2)
        const float c4 = -0.3606737602222409f;   // -1/(4 ln2)
        return x * fmaf(x, fmaf(x, fmaf(x, c4, c3), c2), c1);
    }
    return log2f(1.0f + x);                      // rare fallback, exact regime
}

__global__ __launch_bounds__(NTHR, 2) void k_main(
    const float* __restrict__ ta, const float* __restrict__ pa,
    const float* __restrict__ ca, const float* __restrict__ cres,
    const float* __restrict__ pl, const float* __restrict__ tsize,
    const void* __restrict__ eidx, float* __restrict__ out)
{
    // Dynamic smem: per-edge stash for phase 2 (10 B/edge)
    extern __shared__ char smem_raw[];
    float*          s_pw    = (float*)smem_raw;                 // [ITERS*NTHR]
    float*          s_tasks = s_pw + ITERS * NTHR;              // [ITERS*NTHR]
    unsigned short* s_srv   = (unsigned short*)(s_tasks + ITERS * NTHR);

    __shared__ float  srv[N_SERVERS];    // phase2: global server sums
    __shared__ float  s_cres[N_SERVERS]; // compute_resource, smem gather
    __shared__ double sacc[NWARPS];

    const int tid   = threadIdx.x;
    const int warp  = tid >> 5;
    const int lane  = tid & 31;
    const int gwarp = blockIdx.x * NWARPS + warp;
    const bool is64 = idx_is64(eidx);

    for (int i = tid; i < N_SERVERS; i += NTHR) s_cres[i] = cres[i];
    __syncthreads();

    float acc = 0.0f;

    // ------- Phase 1: softmaxes (no max pass: inputs in [0,1]), per-server pw
    //         sums via direct global RED (L2 atomic ALU, off the SM's L1 pipe),
    //         comp term; stash pw/tasks/server in smem for phase 2.
#pragma unroll
    for (int it = 0; it < ITERS; ++it) {
        const int u = gwarp + it * NWARP_G;
        if (u < N_USERS) {
            const int e = u * DEG + lane;
            float vt = __expf(ta[e]);
            float vp = __expf(pa[e]);
            float vc = __expf(ca[e]);
            float st = vt, sp = vp, sc = vc;
#pragma unroll
            for (int o = 16; o > 0; o >>= 1) {    // 3 interleaved reductions (ILP)
                st += __shfl_xor_sync(0xffffffffu, st, o);
                sp += __shfl_xor_sync(0xffffffffu, sp, o);
                sc += __shfl_xor_sync(0xffffffffu, sc, o);
            }
            const float tsche = __fdividef(vt, st + 1e-16f);
            const float psche = __fdividef(vp, sp + 1e-16f);
            const float csche = __fdividef(vc, sc + 1e-16f);

            const int   s     = load_server(eidx, e, is64);
            const float tasks = tsize[u] * tsche;
            const float comp  = s_cres[s] * csche;
            const float pw    = psche * pl[e];

            const int slot = it * NTHR + tid;
            s_pw[slot]    = pw;
            s_tasks[slot] = tasks;
            s_srv[slot]   = (unsigned short)s;

            atomicAdd(&g_ssum[s], pw);            // RED.ADD.F32 (no return)
            acc += __fdividef(tasks, comp + 1e-20f);
        }
    }

    grid_barrier(1);                 // all server sums globally visible

    for (int i = tid; i < N_SERVERS; i += NTHR) srv[i] = g_ssum[i];
    __syncthreads();

    // ------- Phase 2: rate term, entirely from smem + poly log
#pragma unroll
    for (int it = 0; it < ITERS; ++it) {
        const int u = gwarp + it * NWARP_G;
        if (u < N_USERS) {
            const int   slot = it * NTHR + tid;
            const int   s    = s_srv[slot];
            const float pw   = s_pw[slot];
            const float intf = srv[s] - pw;
            const float x    = __fdividef(pw, intf + 1e-9f);
            const float rate = log2_1p(x);
            acc += __fdividef(s_tasks[slot], rate + 1e-20f);
        }
    }

    // ------- Reduce acc -> g_acc
#pragma unroll
    for (int o = 16; o > 0; o >>= 1)
        acc += __shfl_xor_sync(0xffffffffu, acc, o);
    if (lane == 0) sacc[warp] = (double)acc;
    __syncthreads();
    if (warp == 0) {
        double v = (tid < NWARPS) ? sacc[tid] : 0.0;
#pragma unroll
        for (int o = 16; o > 0; o >>= 1)
            v += __shfl_xor_sync(0xffffffffu, v, o);
        if (tid == 0) atomicAdd(&g_acc, v);
    }

    grid_barrier(0);                 // all partials landed; flag back to 0

    // Block 0 writes the result and re-zeros persistent state for next replay.
    if (blockIdx.x == 0) {
        if (tid == 0) {
            out[0] = (float)(g_acc / (double)N_USERS);
            g_acc = 0.0;
        }
        if (tid < N_SERVERS) g_ssum[tid] = 0.0f;
    }
}

extern "C" void kernel_launch(void* const* d_in, const int* in_sizes, int n_in,
                              void* d_out, int out_size)
{
    // metadata order:
    // 0 compute_resource [512] f32
    // 1 path_losses      [E]   f32
    // 2 task_size        [50000] f32
    // 3 edge_index       [2,E] int (32 or 64, detected on device)
    // 4 task_allocation  [E,1] f32
    // 5 power_allocation [E,1] f32
    // 6 comp_allocation  [E,1] f32
    const float* cres  = (const float*)d_in[0];
    const float* pl    = (const float*)d_in[1];
    const float* tsize = (const float*)d_in[2];
    const void*  eidx  = d_in[3];
    const float* ta    = (const float*)d_in[4];
    const float* pa    = (const float*)d_in[5];
    const float* ca    = (const float*)d_in[6];
    float* out = (float*)d_out;

    const size_t dyn_smem = (size_t)ITERS * NTHR * (4 + 4 + 2);  // 61440 B

    static bool attr_done = false;
    if (!attr_done) {
        cudaFuncSetAttribute(k_main, cudaFuncAttributeMaxDynamicSharedMemorySize,
                             (int)dyn_smem);
        attr_done = true;
    }

    k_main<<<NBLK, NTHR, dyn_smem>>>(ta, pa, ca, cres, pl, tsize, eidx, out);
}

// round 6
// speedup vs baseline: 9.6149x; 9.6149x over previous
#include <cuda_runtime.h>

#define N_USERS   50000
#define DEG       32
#define N_EDGES   (N_USERS * DEG)
#define N_SERVERS 512

#define NBLK    296                                  // 2 CTAs per SM, single wave
#define NTHR    1024
#define NWARPS  (NTHR / 32)
#define NWARP_G (NBLK * NWARPS)                      // 9472 warps
#define ITERS   ((N_USERS + NWARP_G - 1) / NWARP_G)  // 6

// Persistent state (allocation-free; self-cleaning, no zeroing kernel)
__device__ float        g_ssum[N_SERVERS];  // zero-init; re-zeroed each run
__device__ double       g_acc;              // zero-init; re-zeroed each run
__device__ unsigned     g_cnt;              // barrier counter, self-resetting
__device__ volatile int g_flag;             // barrier sense, returns to 0 each run

// ---------------------------------------------------------------------------
// dtype detection for edge_index: user_index = repeat(arange(50000), 32).
// As u64 words, word[16] (bytes 128..135):
//   int64 storage: user64[16] = 0
//   int32 storage: packs user32[32]=1,user32[33]=1 -> 0x0000000100000001
// ---------------------------------------------------------------------------
__device__ __forceinline__ bool idx_is64(const void* eidx) {
    return ((const unsigned long long*)eidx)[16] == 0ull;
}
__device__ __forceinline__ int load_server(const void* eidx, int e, bool is64) {
    if (is64) return (int)((const long long*)eidx)[N_EDGES + e];
    return ((const int*)eidx)[N_EDGES + e];
}

// Sense-reversing grid barrier. Valid: 296 CTAs = exactly one wave
// (2 CTAs/SM guaranteed by launch_bounds + smem budget -> all resident).
__device__ __forceinline__ void grid_barrier(int sense) {
    __syncthreads();
    if (threadIdx.x == 0) {
        __threadfence();
        unsigned t = atomicAdd(&g_cnt, 1u);
        if (t == NBLK - 1) {
            atomicExch(&g_cnt, 0u);
            __threadfence();
            g_flag = sense;
        } else {
            while (g_flag != sense) { }
        }
        __threadfence();
    }
    __syncthreads();
}

// Accurate log2(1+x) for small x (relative truncation err < x^4/5).
// Validated in R5: rel_err 4.2e-7. Avoids MUFU LG2's absolute-error blowup
// (R3 bug) AND the ~40-instr precise log2f sequence (R4 cost).
__device__ __forceinline__ float log2_1p(float x) {
    if (x < 0.02f) {
        const float c1 =  1.4426950408889634f;   //  1/ln2
        const float c2 = -0.7213475204444817f;   // -1/(2 ln2)
        const float c3 =  0.4808983469629878f;   //  1/(3 ln2)
        const float c4 = -0.3606737602222409f;   // -1/(4 ln2)
        return x * fmaf(x, fmaf(x, fmaf(x, c4, c3), c2), c1);
    }
    return log2f(1.0f + x);                      // rare fallback, exact regime
}

__global__ __launch_bounds__(NTHR, 2) void k_main(
    const float* __restrict__ ta, const float* __restrict__ pa,
    const float* __restrict__ ca, const float* __restrict__ cres,
    const float* __restrict__ pl, const float* __restrict__ tsize,
    const void* __restrict__ eidx, float* __restrict__ out)
{
    // Dynamic smem: per-edge stash for phase 2 (10 B/edge)
    extern __shared__ char smem_raw[];
    float*          s_pw    = (float*)smem_raw;                 // [ITERS*NTHR]
    float*          s_tasks = s_pw + ITERS * NTHR;              // [ITERS*NTHR]
    unsigned short* s_srv   = (unsigned short*)(s_tasks + ITERS * NTHR);

    __shared__ float  srv[N_SERVERS];    // phase1: block-local pw sums; phase2: global sums
    __shared__ float  s_cres[N_SERVERS]; // compute_resource, smem gather
    __shared__ double sacc[NWARPS];

    const int tid   = threadIdx.x;
    const int warp  = tid >> 5;
    const int lane  = tid & 31;
    const int gwarp = blockIdx.x * NWARPS + warp;
    const bool is64 = idx_is64(eidx);

    for (int i = tid; i < N_SERVERS; i += NTHR) {
        srv[i]    = 0.0f;
        s_cres[i] = cres[i];
    }
    __syncthreads();

    float acc = 0.0f;

    // ------- Phase 1: softmaxes (no max pass: inputs in [0,1]), block-local
    //         server pw sums in smem (hierarchical: 1.6M edge atomics compress
    //         to 296*512 global atomics at flush — R5 showed direct global
    //         RED serializes at the L2 per-address ALU, 9x slower overall).
#pragma unroll
    for (int it = 0; it < ITERS; ++it) {
        const int u = gwarp + it * NWARP_G;
        if (u < N_USERS) {
            const int e = u * DEG + lane;
            float vt = __expf(ta[e]);
            float vp = __expf(pa[e]);
            float vc = __expf(ca[e]);
            float st = vt, sp = vp, sc = vc;
#pragma unroll
            for (int o = 16; o > 0; o >>= 1) {    // 3 interleaved reductions (ILP)
                st += __shfl_xor_sync(0xffffffffu, st, o);
                sp += __shfl_xor_sync(0xffffffffu, sp, o);
                sc += __shfl_xor_sync(0xffffffffu, sc, o);
            }
            const float tsche = __fdividef(vt, st + 1e-16f);
            const float psche = __fdividef(vp, sp + 1e-16f);
            const float csche = __fdividef(vc, sc + 1e-16f);

            const int   s     = load_server(eidx, e, is64);
            const float tasks = tsize[u] * tsche;
            const float comp  = s_cres[s] * csche;
            const float pw    = psche * pl[e];

            const int slot = it * NTHR + tid;
            s_pw[slot]    = pw;
            s_tasks[slot] = tasks;
            s_srv[slot]   = (unsigned short)s;

            atomicAdd(&srv[s], pw);               // smem ATOMS (block-local)
            acc += __fdividef(tasks, comp + 1e-20f);
        }
    }

    __syncthreads();
    for (int i = tid; i < N_SERVERS; i += NTHR)
        atomicAdd(&g_ssum[i], srv[i]);            // 512 adds per block only

    grid_barrier(1);                 // all server sums globally visible

    for (int i = tid; i < N_SERVERS; i += NTHR) srv[i] = g_ssum[i];
    __syncthreads();

    // ------- Phase 2: rate term, entirely from smem + poly log
#pragma unroll
    for (int it = 0; it < ITERS; ++it) {
        const int u = gwarp + it * NWARP_G;
        if (u < N_USERS) {
            const int   slot = it * NTHR + tid;
            const int   s    = s_srv[slot];
            const float pw   = s_pw[slot];
            const float intf = srv[s] - pw;
            const float x    = __fdividef(pw, intf + 1e-9f);
            const float rate = log2_1p(x);
            acc += __fdividef(s_tasks[slot], rate + 1e-20f);
        }
    }

    // ------- Reduce acc -> g_acc
#pragma unroll
    for (int o = 16; o > 0; o >>= 1)
        acc += __shfl_xor_sync(0xffffffffu, acc, o);
    if (lane == 0) sacc[warp] = (double)acc;
    __syncthreads();
    if (warp == 0) {
        double v = (tid < NWARPS) ? sacc[tid] : 0.0;
#pragma unroll
        for (int o = 16; o > 0; o >>= 1)
            v += __shfl_xor_sync(0xffffffffu, v, o);
        if (tid == 0) atomicAdd(&g_acc, v);
    }

    grid_barrier(0);                 // all partials landed; flag back to 0

    // Block 0 writes the result and re-zeros persistent state for next replay.
    if (blockIdx.x == 0) {
        if (tid == 0) {
            out[0] = (float)(g_acc / (double)N_USERS);
            g_acc = 0.0;
        }
        if (tid < N_SERVERS) g_ssum[tid] = 0.0f;
    }
}

extern "C" void kernel_launch(void* const* d_in, const int* in_sizes, int n_in,
                              void* d_out, int out_size)
{
    // metadata order:
    // 0 compute_resource [512] f32
    // 1 path_losses      [E]   f32
    // 2 task_size        [50000] f32
    // 3 edge_index       [2,E] int (32 or 64, detected on device)
    // 4 task_allocation  [E,1] f32
    // 5 power_allocation [E,1] f32
    // 6 comp_allocation  [E,1] f32
    const float* cres  = (const float*)d_in[0];
    const float* pl    = (const float*)d_in[1];
    const float* tsize = (const float*)d_in[2];
    const void*  eidx  = d_in[3];
    const float* ta    = (const float*)d_in[4];
    const float* pa    = (const float*)d_in[5];
    const float* ca    = (const float*)d_in[6];
    float* out = (float*)d_out;

    const size_t dyn_smem = (size_t)ITERS * NTHR * (4 + 4 + 2);  // 61440 B

    static bool attr_done = false;
    if (!attr_done) {
        cudaFuncSetAttribute(k_main, cudaFuncAttributeMaxDynamicSharedMemorySize,
                             (int)dyn_smem);
        attr_done = true;
    }

    k_main<<<NBLK, NTHR, dyn_smem>>>(ta, pa, ca, cres, pl, tsize, eidx, out);
}

// round 8
// speedup vs baseline: 9.7218x; 1.0111x over previous
#include <cuda_runtime.h>

#define N_USERS   50000
#define DEG       32
#define N_EDGES   (N_USERS * DEG)
#define N_SERVERS 512

#define NBLK    296                                  // 2 CTAs per SM, single wave
#define NTHR    1024
#define NWARPS  (NTHR / 32)
#define NWARP_G (NBLK * NWARPS)                      // 9472 warps
#define ITERS   ((N_USERS + NWARP_G - 1) / NWARP_G)  // 6

// Persistent state (allocation-free; self-cleaning, no zeroing kernel)
__device__ float        g_ssum[N_SERVERS];  // zero-init; re-zeroed each run
__device__ double       g_acc;              // zero-init; re-zeroed each run
__device__ unsigned     g_cnt;              // barrier counter, self-resetting
__device__ volatile int g_flag;             // barrier flag; reset by last block
__device__ unsigned     g_done;             // completion counter, self-resetting

// ---------------------------------------------------------------------------
// dtype detection for edge_index: user_index = repeat(arange(50000), 32).
// As u64 words, word[16] (bytes 128..135):
//   int64 storage: user64[16] = 0
//   int32 storage: packs user32[32]=1,user32[33]=1 -> 0x0000000100000001
// ---------------------------------------------------------------------------
__device__ __forceinline__ bool idx_is64(const void* eidx) {
    return ((const unsigned long long*)eidx)[16] == 0ull;
}
__device__ __forceinline__ int load_server(const void* eidx, int e, bool is64) {
    if (is64) return (int)((const long long*)eidx)[N_EDGES + e];
    return ((const int*)eidx)[N_EDGES + e];
}

// Single grid barrier (phase fence). Valid: 296 CTAs = exactly one wave
// (2 CTAs/SM guaranteed by launch_bounds + smem budget -> all resident).
// g_cnt self-resets here; g_flag is reset by the last-done block at the end.
__device__ __forceinline__ void grid_barrier_once() {
    __syncthreads();
    if (threadIdx.x == 0) {
        __threadfence();
        unsigned t = atomicAdd(&g_cnt, 1u);
        if (t == NBLK - 1) {
            atomicExch(&g_cnt, 0u);
            __threadfence();
            g_flag = 1;
        } else {
            while (g_flag != 1) { }
        }
        __threadfence();
    }
    __syncthreads();
}

// Accurate log2(1+x) for small x (relative truncation err < x^4/5).
// Validated R5/R6: rel_err ~4e-7. Avoids MUFU LG2's absolute-error blowup
// (R3 bug) AND the ~40-instr precise log2f sequence (R4 cost).
__device__ __forceinline__ float log2_1p(float x) {
    if (x < 0.02f) {
        const float c1 =  1.4426950408889634f;   //  1/ln2
        const float c2 = -0.7213475204444817f;   // -1/(2 ln2)
        const float c3 =  0.4808983469629878f;   //  1/(3 ln2)
        const float c4 = -0.3606737602222409f;   // -1/(4 ln2)
        return x * fmaf(x, fmaf(x, fmaf(x, c4, c3), c2), c1);
    }
    return log2f(1.0f + x);                      // rare fallback, exact regime
}

__global__ __launch_bounds__(NTHR, 2) void k_main(
    const float* __restrict__ ta, const float* __restrict__ pa,
    const float* __restrict__ ca, const float* __restrict__ cres,
    const float* __restrict__ pl, const float* __restrict__ tsize,
    const void* __restrict__ eidx, float* __restrict__ out)
{
    // Dynamic smem: per-edge stash for phase 2 (10 B/edge)
    extern __shared__ char smem_raw[];
    float*          s_pw    = (float*)smem_raw;                 // [ITERS*NTHR]
    float*          s_tasks = s_pw + ITERS * NTHR;              // [ITERS*NTHR]
    unsigned short* s_srv   = (unsigned short*)(s_tasks + ITERS * NTHR);

    __shared__ float  srv[N_SERVERS];    // phase1: block-local pw sums; phase2: global sums
    __shared__ float  s_cres[N_SERVERS]; // compute_resource, smem gather
    __shared__ double sacc[NWARPS];

    const int tid   = threadIdx.x;
    const int warp  = tid >> 5;
    const int lane  = tid & 31;
    const int gwarp = blockIdx.x * NWARPS + warp;
    const bool is64 = idx_is64(eidx);

    for (int i = tid; i < N_SERVERS; i += NTHR) {
        srv[i]    = 0.0f;
        s_cres[i] = cres[i];
    }
    __syncthreads();

    float acc = 0.0f;

    // ------- Phase 1: softmaxes (no max pass: inputs in [0,1]); block-local
    //         server pw sums in smem (hierarchical — R5 proved direct global
    //         RED to 512 addresses serializes at L2, 9x slower).
    //         NOTE: redux.sync.add.f32 does NOT exist on sm_103 (R7 ptxas
    //         failure) — interleaved SHFL butterflies are the minimum here.
#pragma unroll
    for (int it = 0; it < ITERS; ++it) {
        const int u = gwarp + it * NWARP_G;
        if (u < N_USERS) {
            const int e = u * DEG + lane;
            const float vt = __expf(ta[e]);
            const float vp = __expf(pa[e]);
            const float vc = __expf(ca[e]);
            float st = vt, sp = vp, sc = vc;
#pragma unroll
            for (int o = 16; o > 0; o >>= 1) {    // 3 interleaved reductions (ILP)
                st += __shfl_xor_sync(0xffffffffu, st, o);
                sp += __shfl_xor_sync(0xffffffffu, sp, o);
                sc += __shfl_xor_sync(0xffffffffu, sc, o);
            }
            const float tsche = __fdividef(vt, st + 1e-16f);
            const float psche = __fdividef(vp, sp + 1e-16f);
            const float csche = __fdividef(vc, sc + 1e-16f);

            const int   s     = load_server(eidx, e, is64);
            const float tasks = tsize[u] * tsche;
            const float comp  = s_cres[s] * csche;
            const float pw    = psche * pl[e];

            const int slot = it * NTHR + tid;
            s_pw[slot]    = pw;
            s_tasks[slot] = tasks;
            s_srv[slot]   = (unsigned short)s;

            atomicAdd(&srv[s], pw);               // smem ATOMS (block-local)
            acc += __fdividef(tasks, comp + 1e-20f);
        }
    }

    __syncthreads();
    for (int i = tid; i < N_SERVERS; i += NTHR)
        atomicAdd(&g_ssum[i], srv[i]);            // 512 adds per block only

    grid_barrier_once();             // all server sums globally visible

    for (int i = tid; i < N_SERVERS; i += NTHR) srv[i] = g_ssum[i];
    __syncthreads();

    // ------- Phase 2: rate term, entirely from smem + poly log
#pragma unroll
    for (int it = 0; it < ITERS; ++it) {
        const int u = gwarp + it * NWARP_G;
        if (u < N_USERS) {
            const int   slot = it * NTHR + tid;
            const int   s    = s_srv[slot];
            const float pw   = s_pw[slot];
            const float intf = srv[s] - pw;
            const float x    = __fdividef(pw, intf + 1e-9f);
            const float rate = log2_1p(x);
            acc += __fdividef(s_tasks[slot], rate + 1e-20f);
        }
    }

    // ------- Reduce acc -> g_acc, then last-done block finalizes
#pragma unroll
    for (int o = 16; o > 0; o >>= 1)
        acc += __shfl_xor_sync(0xffffffffu, acc, o);
    if (lane == 0) sacc[warp] = (double)acc;
    __syncthreads();
    if (warp == 0) {
        double v = (tid < NWARPS) ? sacc[tid] : 0.0;
#pragma unroll
        for (int o = 16; o > 0; o >>= 1)
            v += __shfl_xor_sync(0xffffffffu, v, o);
        if (tid == 0) {
            atomicAdd(&g_acc, v);
            __threadfence();
            // Last-done block writes the result and resets persistent state
            // (no second grid barrier; 295 blocks exit immediately).
            unsigned d = atomicAdd(&g_done, 1u);
            if (d == NBLK - 1) {
                atomicExch(&g_done, 0u);
                out[0] = (float)(g_acc / (double)N_USERS);
                g_acc  = 0.0;
                g_flag = 0;
                for (int i = 0; i < N_SERVERS; ++i) g_ssum[i] = 0.0f;
                __threadfence();
            }
        }
    }
}

extern "C" void kernel_launch(void* const* d_in, const int* in_sizes, int n_in,
                              void* d_out, int out_size)
{
    // metadata order:
    // 0 compute_resource [512] f32
    // 1 path_losses      [E]   f32
    // 2 task_size        [50000] f32
    // 3 edge_index       [2,E] int (32 or 64, detected on device)
    // 4 task_allocation  [E,1] f32
    // 5 power_allocation [E,1] f32
    // 6 comp_allocation  [E,1] f32
    const float* cres  = (const float*)d_in[0];
    const float* pl    = (const float*)d_in[1];
    const float* tsize = (const float*)d_in[2];
    const void*  eidx  = d_in[3];
    const float* ta    = (const float*)d_in[4];
    const float* pa    = (const float*)d_in[5];
    const float* ca    = (const float*)d_in[6];
    float* out = (float*)d_out;

    const size_t dyn_smem = (size_t)ITERS * NTHR * (4 + 4 + 2);  // 61440 B

    static bool attr_done = false;
    if (!attr_done) {
        cudaFuncSetAttribute(k_main, cudaFuncAttributeMaxDynamicSharedMemorySize,
                             (int)dyn_smem);
        attr_done = true;
    }

    k_main<<<NBLK, NTHR, dyn_smem>>>(ta, pa, ca, cres, pl, tsize, eidx, out);
}

// round 9
// speedup vs baseline: 10.6718x; 1.0977x over previous
#include <cuda_runtime.h>

#define N_USERS   50000
#define DEG       32
#define N_EDGES   (N_USERS * DEG)
#define N_SERVERS 512

#define NBLK    148                                   // 1 CTA per SM, single wave
#define NTHR    1024
#define NWARPS  (NTHR / 32)
#define NWARP_G (NBLK * NWARPS)                       // 4736 warps
#define NQUADS  (N_USERS / 4)                         // 12500 user-quads
#define QITERS  ((NQUADS + NWARP_G - 1) / NWARP_G)    // 3

// Persistent state (allocation-free; self-cleaning, no zeroing kernel)
__device__ float        g_ssum[N_SERVERS];  // zero-init; re-zeroed each run
__device__ double       g_acc;              // zero-init; re-zeroed each run
__device__ unsigned     g_cnt;              // barrier counter, self-resetting
__device__ volatile int g_flag;             // barrier flag; reset by last block
__device__ unsigned     g_done;             // completion counter, self-resetting

// ---------------------------------------------------------------------------
// dtype detection for edge_index: user_index = repeat(arange(50000), 32).
// As u64 words, word[16] (bytes 128..135):
//   int64 storage: user64[16] = 0
//   int32 storage: packs user32[32]=1,user32[33]=1 -> 0x0000000100000001
// ---------------------------------------------------------------------------
__device__ __forceinline__ bool idx_is64(const void* eidx) {
    return ((const unsigned long long*)eidx)[16] == 0ull;
}

// Single grid barrier (phase fence). Valid: 148 CTAs = exactly one wave
// (1 CTA/SM). g_cnt self-resets; g_flag is reset by the last-done block.
__device__ __forceinline__ void grid_barrier_once() {
    __syncthreads();
    if (threadIdx.x == 0) {
        __threadfence();
        unsigned t = atomicAdd(&g_cnt, 1u);
        if (t == NBLK - 1) {
            atomicExch(&g_cnt, 0u);
            __threadfence();
            g_flag = 1;
        } else {
            while (g_flag != 1) { }
        }
        __threadfence();
    }
    __syncthreads();
}

// Accurate log2(1+x) for small x (relative truncation err < x^4/5).
// Validated R5-R8: rel_err ~4e-7. Avoids MUFU LG2's absolute-error blowup
// (R3 bug) AND the ~40-instr precise log2f sequence (R4 cost).
__device__ __forceinline__ float log2_1p(float x) {
    if (x < 0.02f) {
        const float c1 =  1.4426950408889634f;   //  1/ln2
        const float c2 = -0.7213475204444817f;   // -1/(2 ln2)
        const float c3 =  0.4808983469629878f;   //  1/(3 ln2)
        const float c4 = -0.3606737602222409f;   // -1/(4 ln2)
        return x * fmaf(x, fmaf(x, fmaf(x, c4, c3), c2), c1);
    }
    return log2f(1.0f + x);                      // rare fallback, exact regime
}

// Sum the 4 in-thread values + 3-xor butterfly over the 8-lane group that
// shares one user. Result broadcast to all 8 lanes.
__device__ __forceinline__ float group8_sum(float4 v) {
    float s = (v.x + v.y) + (v.z + v.w);
    s += __shfl_xor_sync(0xffffffffu, s, 4);
    s += __shfl_xor_sync(0xffffffffu, s, 2);
    s += __shfl_xor_sync(0xffffffffu, s, 1);
    return s;
}

__global__ __launch_bounds__(NTHR, 1) void k_main(
    const float* __restrict__ ta, const float* __restrict__ pa,
    const float* __restrict__ ca, const float* __restrict__ cres,
    const float* __restrict__ pl, const float* __restrict__ tsize,
    const void* __restrict__ eidx, float* __restrict__ out)
{
    // Dynamic smem stash: per thread-iter 2 float4 {pw,task}x4 + 1 ushort4 srv.
    extern __shared__ char smem_raw[];
    float4*  s_pwt = (float4*)smem_raw;                      // [QITERS*NTHR*2]
    ushort4* s_srv = (ushort4*)(smem_raw + QITERS * NTHR * 2 * sizeof(float4));

    __shared__ float  srv[N_SERVERS];    // phase1: block-local pw sums; phase2: global
    __shared__ float  s_cres[N_SERVERS];
    __shared__ double sacc[NWARPS];

    const int tid  = threadIdx.x;
    const int warp = tid >> 5;
    const int lane = tid & 31;
    // Transposed warp mapping: every block gets the same 3-iter/2-iter warp mix,
    // so per-SM work is balanced (R8 tail-imbalance fix).
    const int wt   = warp * NBLK + blockIdx.x;
    const bool is64 = idx_is64(eidx);

    for (int i = tid; i < N_SERVERS; i += NTHR) {
        srv[i]    = 0.0f;
        s_cres[i] = cres[i];
    }
    __syncthreads();

    float acc = 0.0f;

    // ------- Phase 1: 4 users per warp-iter. 8 lanes per user, 4 edges/lane.
    //         Vector LDG.128, 3 shuffles per softmax sum (for 4 users at once),
    //         1 rcp per user-sum. smem ATOMS per edge (hierarchical; R5 proved
    //         direct global RED to 512 addresses is 9x slower).
#pragma unroll
    for (int it = 0; it < QITERS; ++it) {
        const int q = wt + it * NWARP_G;
        if (q < NQUADS) {
            const int ug    = q * 4 + (lane >> 3);       // this lane's user
            const int ebase = ug * DEG + (lane & 7) * 4; // 4 consecutive edges

            const float4 t4  = *(const float4*)(ta + ebase);
            const float4 p4  = *(const float4*)(pa + ebase);
            const float4 c4  = *(const float4*)(ca + ebase);
            const float4 pl4 = *(const float4*)(pl + ebase);

            const float4 vt = make_float4(__expf(t4.x), __expf(t4.y), __expf(t4.z), __expf(t4.w));
            const float4 vp = make_float4(__expf(p4.x), __expf(p4.y), __expf(p4.z), __expf(p4.w));
            const float4 vc = make_float4(__expf(c4.x), __expf(c4.y), __expf(c4.z), __expf(c4.w));

            const float st = group8_sum(vt);
            const float sp = group8_sum(vp);
            const float sc = group8_sum(vc);
            const float rt_ = __fdividef(1.0f, st + 1e-16f);
            const float rp_ = __fdividef(1.0f, sp + 1e-16f);
            const float rc_ = __fdividef(1.0f, sc + 1e-16f);

            const float ts = tsize[ug];

            int s0, s1, s2, s3;
            if (is64) {
                const ulonglong2* sp64 =
                    (const ulonglong2*)((const long long*)eidx + N_EDGES + ebase);
                const ulonglong2 a = sp64[0], b = sp64[1];
                s0 = (int)a.x; s1 = (int)a.y; s2 = (int)b.x; s3 = (int)b.y;
            } else {
                const int4 si = *(const int4*)((const int*)eidx + N_EDGES + ebase);
                s0 = si.x; s1 = si.y; s2 = si.z; s3 = si.w;
            }

            const float task0 = ts * (vt.x * rt_), task1 = ts * (vt.y * rt_);
            const float task2 = ts * (vt.z * rt_), task3 = ts * (vt.w * rt_);
            const float pw0 = (vp.x * rp_) * pl4.x, pw1 = (vp.y * rp_) * pl4.y;
            const float pw2 = (vp.z * rp_) * pl4.z, pw3 = (vp.w * rp_) * pl4.w;

            atomicAdd(&srv[s0], pw0);
            atomicAdd(&srv[s1], pw1);
            atomicAdd(&srv[s2], pw2);
            atomicAdd(&srv[s3], pw3);

            acc += __fdividef(task0, s_cres[s0] * (vc.x * rc_) + 1e-20f);
            acc += __fdividef(task1, s_cres[s1] * (vc.y * rc_) + 1e-20f);
            acc += __fdividef(task2, s_cres[s2] * (vc.z * rc_) + 1e-20f);
            acc += __fdividef(task3, s_cres[s3] * (vc.w * rc_) + 1e-20f);

            const int idx = it * NTHR + tid;
            s_pwt[idx * 2 + 0] = make_float4(pw0, task0, pw1, task1);
            s_pwt[idx * 2 + 1] = make_float4(pw2, task2, pw3, task3);
            s_srv[idx] = make_ushort4((unsigned short)s0, (unsigned short)s1,
                                      (unsigned short)s2, (unsigned short)s3);
        }
    }

    __syncthreads();
    for (int i = tid; i < N_SERVERS; i += NTHR)
        atomicAdd(&g_ssum[i], srv[i]);            // 512 adds per block only

    grid_barrier_once();             // all server sums globally visible

    for (int i = tid; i < N_SERVERS; i += NTHR) srv[i] = g_ssum[i];
    __syncthreads();

    // ------- Phase 2: rate term, entirely from smem + poly log
#pragma unroll
    for (int it = 0; it < QITERS; ++it) {
        const int q = wt + it * NWARP_G;
        if (q < NQUADS) {
            const int     idx = it * NTHR + tid;
            const float4  a   = s_pwt[idx * 2 + 0];
            const float4  b   = s_pwt[idx * 2 + 1];
            const ushort4 sv  = s_srv[idx];

            float intf, x;
            intf = srv[sv.x] - a.x; x = __fdividef(a.x, intf + 1e-9f);
            acc += __fdividef(a.y, log2_1p(x) + 1e-20f);
            intf = srv[sv.y] - a.z; x = __fdividef(a.z, intf + 1e-9f);
            acc += __fdividef(a.w, log2_1p(x) + 1e-20f);
            intf = srv[sv.z] - b.x; x = __fdividef(b.x, intf + 1e-9f);
            acc += __fdividef(b.y, log2_1p(x) + 1e-20f);
            intf = srv[sv.w] - b.z; x = __fdividef(b.z, intf + 1e-9f);
            acc += __fdividef(b.w, log2_1p(x) + 1e-20f);
        }
    }

    // ------- Reduce acc -> g_acc, then last-done block finalizes
#pragma unroll
    for (int o = 16; o > 0; o >>= 1)
        acc += __shfl_xor_sync(0xffffffffu, acc, o);
    if (lane == 0) sacc[warp] = (double)acc;
    __syncthreads();
    if (warp == 0) {
        double v = (tid < NWARPS) ? sacc[tid] : 0.0;
#pragma unroll
        for (int o = 16; o > 0; o >>= 1)
            v += __shfl_xor_sync(0xffffffffu, v, o);
        if (tid == 0) {
            atomicAdd(&g_acc, v);
            __threadfence();
            // Last-done block writes the result and resets persistent state
            // (no second grid barrier; other blocks exit immediately).
            unsigned d = atomicAdd(&g_done, 1u);
            if (d == NBLK - 1) {
                atomicExch(&g_done, 0u);
                out[0] = (float)(g_acc / (double)N_USERS);
                g_acc  = 0.0;
                g_flag = 0;
                for (int i = 0; i < N_SERVERS; ++i) g_ssum[i] = 0.0f;
                __threadfence();
            }
        }
    }
}

extern "C" void kernel_launch(void* const* d_in, const int* in_sizes, int n_in,
                              void* d_out, int out_size)
{
    // metadata order:
    // 0 compute_resource [512] f32
    // 1 path_losses      [E]   f32
    // 2 task_size        [50000] f32
    // 3 edge_index       [2,E] int (32 or 64, detected on device)
    // 4 task_allocation  [E,1] f32
    // 5 power_allocation [E,1] f32
    // 6 comp_allocation  [E,1] f32
    const float* cres  = (const float*)d_in[0];
    const float* pl    = (const float*)d_in[1];
    const float* tsize = (const float*)d_in[2];
    const void*  eidx  = d_in[3];
    const float* ta    = (const float*)d_in[4];
    const float* pa    = (const float*)d_in[5];
    const float* ca    = (const float*)d_in[6];
    float* out = (float*)d_out;

    const size_t dyn_smem = (size_t)QITERS * NTHR * (2 * sizeof(float4) + sizeof(ushort4));
    // = 3*1024*40 = 122880 B (fits: 1 CTA/SM, 228KB limit)

    static bool attr_done = false;
    if (!attr_done) {
        cudaFuncSetAttribute(k_main, cudaFuncAttributeMaxDynamicSharedMemorySize,
                             (int)dyn_smem);
        attr_done = true;
    }

    k_main<<<NBLK, NTHR, dyn_smem>>>(ta, pa, ca, cres, pl, tsize, eidx, out);
}